// round 5
// baseline (speedup 1.0000x reference)
#include <cuda_runtime.h>
#include <math.h>
#include <stdint.h>

#define D_MODEL 1024
#define N_HEAD  16
#define D_HEAD  64
#define N_CTX   2048
#define BATCH   2
#define MTOT    (BATCH * N_CTX)   /* 4096 rows */

// ---------------- scratch ----------------
__device__ float g_q[MTOT * D_MODEL];
__device__ float g_k[MTOT * D_MODEL];
__device__ float g_v[MTOT * D_MODEL];
__device__ float g_z[MTOT * D_MODEL];
__device__ float g_cos[N_CTX * 32];
__device__ float g_sin[N_CTX * 32];

// ---------------- helpers ----------------
__device__ __forceinline__ float ftf(float x) {
    uint32_t u;
    asm("cvt.rna.tf32.f32 %0, %1;" : "=r"(u) : "f"(x));
    return __uint_as_float(u);
}

__device__ __forceinline__ void mma8(float c[4], const float a[4], const float b[2]) {
    asm volatile(
        "mma.sync.aligned.m16n8k8.row.col.f32.tf32.tf32.f32 "
        "{%0,%1,%2,%3}, {%4,%5,%6,%7}, {%8,%9}, {%0,%1,%2,%3};\n"
        : "+f"(c[0]), "+f"(c[1]), "+f"(c[2]), "+f"(c[3])
        : "r"(__float_as_uint(a[0])), "r"(__float_as_uint(a[1])),
          "r"(__float_as_uint(a[2])), "r"(__float_as_uint(a[3])),
          "r"(__float_as_uint(b[0])), "r"(__float_as_uint(b[1])));
}

// ---------------- RoPE table ----------------
__global__ void rope_cache_kernel() {
    int i = blockIdx.x * blockDim.x + threadIdx.x;
    int t = i >> 5;
    int j = i & 31;
    float invf = (float)pow(10000.0, -(double)j / 32.0);
    double ang = (double)t * (double)invf;
    double sv, cv;
    sincos(ang, &sv, &cv);
    g_cos[i] = (float)cv;
    g_sin[i] = (float)sv;
}

// ---------------- TF32 GEMM, double-buffered, multi-job ----------------
struct GemmJobs {
    const float* W[3];
    const float* bias[3];
    const float* res[3];
    float*       out[3];
};

__global__ __launch_bounds__(256, 2)
void gemm_tc_kernel(const float* __restrict__ A, GemmJobs jobs, int M, int N, int K)
{
    extern __shared__ float smg[];
    float4* As4 = (float4*)smg;            // 2 bufs x 1024 float4
    float4* Bs4 = (float4*)(smg + 8192);   // 2 bufs x 1024 float4

    const int z = blockIdx.z;
    const float* W    = jobs.W[z];
    const float* bias = jobs.bias[z];
    const float* res  = jobs.res[z];
    float*       C    = jobs.out[z];

    const int tid = threadIdx.x;
    const int lane = tid & 31;
    const int wid = tid >> 5;
    const int wm = wid & 3, wn = wid >> 2;
    const int m0 = blockIdx.y * 128, n0 = blockIdx.x * 128;

    const int amt = tid >> 5, ag = (tid >> 2) & 7, aks = tid & 3;
    const float* Ap = A + (size_t)(m0 + amt * 16 + ag) * K + aks * 8;
    const int bnt = ((tid >> 5) << 1) | (tid & 1);
    const int bg = (tid >> 2) & 7;
    const int bksp = (tid >> 1) & 1;
    const int bxor = bksp | ((bnt & 1) << 1);
    const float* Wp = W + (size_t)(n0 + bnt * 8 + bg) * K + bksp * 16;

    float acc[2][8][4];
#pragma unroll
    for (int mi = 0; mi < 2; mi++)
#pragma unroll
        for (int ni = 0; ni < 8; ni++)
#pragma unroll
            for (int e = 0; e < 4; e++) acc[mi][ni][e] = 0.f;

    float4 av0, av1, av2, av3, wv0, wv1, wv2, wv3;
    // prologue load chunk 0
    av0 = *(const float4*)(Ap);
    av1 = *(const float4*)(Ap + 4);
    av2 = *(const float4*)(Ap + (size_t)8 * K);
    av3 = *(const float4*)(Ap + (size_t)8 * K + 4);
    wv0 = *(const float4*)(Wp);
    wv1 = *(const float4*)(Wp + 4);
    wv2 = *(const float4*)(Wp + 8);
    wv3 = *(const float4*)(Wp + 12);

    int p = 0;
    for (int kt = 0; kt < K; kt += 32) {
        // store staged chunk into buffer p
        {
            float4* Ab = As4 + p * 1024;
            float4* Bb = Bs4 + p * 1024;
            float a0[4] = {av0.x, av0.y, av0.z, av0.w};
            float a1[4] = {av1.x, av1.y, av1.z, av1.w};
            float a2[4] = {av2.x, av2.y, av2.z, av2.w};
            float a3[4] = {av3.x, av3.y, av3.z, av3.w};
            float w0[4] = {wv0.x, wv0.y, wv0.z, wv0.w};
            float w1[4] = {wv1.x, wv1.y, wv1.z, wv1.w};
            float w2[4] = {wv2.x, wv2.y, wv2.z, wv2.w};
            float w3[4] = {wv3.x, wv3.y, wv3.z, wv3.w};
#pragma unroll
            for (int t = 0; t < 4; t++) {
                Ab[(aks * 8 + amt) * 32 + ag * 4 + (t ^ aks)] =
                    make_float4(ftf(a0[t]), ftf(a2[t]), ftf(a1[t]), ftf(a3[t]));
                Bb[(bksp * 16 + bnt) * 32 + bg * 4 + (t ^ bxor)] =
                    make_float4(ftf(w0[t]), ftf(w1[t]), ftf(w2[t]), ftf(w3[t]));
            }
        }
        __syncthreads();
        // prefetch next chunk
        if (kt + 32 < K) {
            av0 = *(const float4*)(Ap + kt + 32);
            av1 = *(const float4*)(Ap + kt + 36);
            av2 = *(const float4*)(Ap + kt + 32 + (size_t)8 * K);
            av3 = *(const float4*)(Ap + kt + 36 + (size_t)8 * K);
            wv0 = *(const float4*)(Wp + kt + 32);
            wv1 = *(const float4*)(Wp + kt + 36);
            wv2 = *(const float4*)(Wp + kt + 40);
            wv3 = *(const float4*)(Wp + kt + 44);
        }
        // compute from buffer p
        {
            const float4* Ab = As4 + p * 1024;
            const float4* Bb = Bs4 + p * 1024;
#pragma unroll
            for (int ksp = 0; ksp < 2; ksp++) {
                float4 bb[8];
#pragma unroll
                for (int ni = 0; ni < 8; ni++) {
                    int nt = wn * 8 + ni;
                    int xv = ksp | ((nt & 1) << 1);
                    int lp = (lane & ~3) | ((lane & 3) ^ xv);
                    bb[ni] = Bb[(ksp * 16 + nt) * 32 + lp];
                }
#pragma unroll
                for (int kh = 0; kh < 2; kh++) {
                    int ks = ksp * 2 + kh;
                    int lpa = (lane & ~3) | ((lane & 3) ^ ks);
                    float a[2][4];
#pragma unroll
                    for (int mi = 0; mi < 2; mi++) {
                        float4 aa = Ab[(ks * 8 + wm * 2 + mi) * 32 + lpa];
                        a[mi][0] = aa.x; a[mi][1] = aa.y; a[mi][2] = aa.z; a[mi][3] = aa.w;
                    }
#pragma unroll
                    for (int mi = 0; mi < 2; mi++)
#pragma unroll
                        for (int ni = 0; ni < 8; ni++) {
                            float b[2];
                            if (kh == 0) { b[0] = bb[ni].x; b[1] = bb[ni].y; }
                            else         { b[0] = bb[ni].z; b[1] = bb[ni].w; }
                            mma8(acc[mi][ni], a[mi], b);
                        }
                }
            }
        }
        p ^= 1;
    }

    const int g = lane >> 2, t = lane & 3;
#pragma unroll
    for (int mi = 0; mi < 2; mi++) {
#pragma unroll
        for (int h = 0; h < 2; h++) {
            int m = m0 + wm * 32 + mi * 16 + h * 8 + g;
#pragma unroll
            for (int ni = 0; ni < 8; ni++) {
                int n = n0 + wn * 64 + ni * 8 + 2 * t;
                float2 v = make_float2(acc[mi][ni][h * 2 + 0], acc[mi][ni][h * 2 + 1]);
                if (bias) { v.x += bias[n]; v.y += bias[n + 1]; }
                if (res) {
                    float2 r = *(const float2*)&res[(size_t)m * N + n];
                    v.x += r.x; v.y += r.y;
                }
                *(float2*)&C[(size_t)m * N + n] = v;
            }
        }
    }
}

// ---------------- fused RMSNorm + RoPE ----------------
__global__ __launch_bounds__(256)
void norm_rope_kernel(float* __restrict__ q, float* __restrict__ k,
                      const float* __restrict__ w)
{
    int gw = (blockIdx.x * blockDim.x + threadIdx.x) >> 5;
    int lane = threadIdx.x & 31;
    int which = gw & 1;
    int row = gw >> 1;
    float* ptr = which ? k : q;

    size_t base = (size_t)(row >> 4) * D_MODEL + (size_t)(row & 15) * 64;
    int s = (row >> 4) & (N_CTX - 1);

    float2 xv = *(float2*)&ptr[base + lane * 2];
    float ss = xv.x * xv.x + xv.y * xv.y;
#pragma unroll
    for (int o = 16; o; o >>= 1) ss += __shfl_xor_sync(0xffffffffu, ss, o);
    float r = rsqrtf(ss * (1.0f / 64.0f) + 1.1920929e-07f);

    float y0 = xv.x * r * w[lane * 2];
    float y1 = xv.y * r * w[lane * 2 + 1];

    int j0 = (2 * lane) & 31;
    int j1 = (2 * lane + 1) & 31;
    float c0 = g_cos[s * 32 + j0], s0 = g_sin[s * 32 + j0];
    float c1 = g_cos[s * 32 + j1], s1 = g_sin[s * 32 + j1];

    float2 o;
    o.x = y0 * c0 - y1 * s0;
    o.y = y1 * c1 + y0 * s1;
    *(float2*)&ptr[base + lane * 2] = o;
}

// ---------------- fused quadratic causal attention, TF32 mma ----------------
// Block: (b, h, q-tile 128). 8 warps, warp owns 16 q-rows x full 64-k tile.
// Q in registers; K/V double-buffered fragment-major smem; P transposed via shfl.
#define ATTN_SMEM (16384 * 4)   /* 65536 B: Ks[2][4096]f + Vs[2][4096]f */

__global__ __launch_bounds__(256, 1)
void attn_tc_kernel(const float* __restrict__ Q, const float* __restrict__ Kg,
                    const float* __restrict__ V, float* __restrict__ Z)
{
    extern __shared__ float sm[];
    const int tid = threadIdx.x;
    const int lane = tid & 31;
    const int wp = tid >> 5;                 // warp 0..7
    const int g = lane >> 2, t = lane & 3;
    const int bh = blockIdx.y;
    const int b = bh >> 4, h = bh & 15;
    const int qt = (int)gridDim.x - 1 - (int)blockIdx.x;   // big tiles first
    const size_t base = (size_t)(b * N_CTX) * D_MODEL + h * 64;
    const int nkt = 2 * qt + 2;

    // ---- Q fragments in registers: warp wp covers q rows qt*128 + wp*16 ----
    const int q0 = qt * 128 + wp * 16;
    float qfrag[8][4];
    {
        const float* qp  = Q + base + (size_t)(q0 + g) * D_MODEL;
        const float* qp8 = qp + (size_t)8 * D_MODEL;
#pragma unroll
        for (int ks = 0; ks < 8; ks++) {
            qfrag[ks][0] = ftf(qp[ks * 8 + t]);
            qfrag[ks][1] = ftf(qp8[ks * 8 + t]);
            qfrag[ks][2] = ftf(qp[ks * 8 + t + 4]);
            qfrag[ks][3] = ftf(qp8[ks * 8 + t + 4]);
        }
    }

    float zacc[8][4];
#pragma unroll
    for (int i = 0; i < 8; i++)
#pragma unroll
        for (int j = 0; j < 4; j++) zacc[i][j] = 0.f;

    // K loader coords: row=krow0+16j, col4 fixed
    const int krow0 = tid >> 4, kcol4 = tid & 15;
    const int kksp = kcol4 >> 2, kcomp = kcol4 & 3, kgK = krow0 & 7;
    // V loader coords: row fixed, col4 = vcol40 + 4j
    const int vrow = tid & 63, vcol40 = tid >> 6;
    const int vcp = vrow >> 4, vtt = vrow & 3, vcomp = (vrow >> 2) & 3;
    const int vg0 = (vcol40 & 1) * 4;

    const float* kbase = Kg + base;
    const float* vbase = V + base;

    float4 kreg[4], vreg[4];
    // prologue: load tile 0
#pragma unroll
    for (int j = 0; j < 4; j++) {
        kreg[j] = *(const float4*)&kbase[(size_t)(krow0 + 16 * j) * D_MODEL + kcol4 * 4];
        vreg[j] = *(const float4*)&vbase[(size_t)vrow * D_MODEL + (vcol40 + 4 * j) * 4];
    }

    const float inv64 = 1.0f / 64.0f;
    const int qr0 = q0 + g;
    const int qr1 = qr0 + 8;
    int p = 0;

    for (int kt = 0; kt < nkt; ++kt) {
        const int ktb = kt * 64;
        // ---- store staged K/V into buffer p ----
        {
            float* KsF = sm + p * 4096;
#pragma unroll
            for (int j = 0; j < 4; j++) {
                int nt = (krow0 >> 3) + 2 * j;
                int bb = (kksp * 8 + nt) * 32 + kgK * 4;
                KsF[(bb + (0 ^ kksp)) * 4 + kcomp] = ftf(kreg[j].x);
                KsF[(bb + (1 ^ kksp)) * 4 + kcomp] = ftf(kreg[j].y);
                KsF[(bb + (2 ^ kksp)) * 4 + kcomp] = ftf(kreg[j].z);
                KsF[(bb + (3 ^ kksp)) * 4 + kcomp] = ftf(kreg[j].w);
            }
            float* VsF = sm + 8192 + p * 4096;
#pragma unroll
            for (int j = 0; j < 4; j++) {
                int dn = (vcol40 >> 1) + 2 * j;
                int bb = (vcp * 8 + dn) * 32 + vg0 * 4 + vtt;
                VsF[(bb + 0)  * 4 + vcomp] = ftf(vreg[j].x);
                VsF[(bb + 4)  * 4 + vcomp] = ftf(vreg[j].y);
                VsF[(bb + 8)  * 4 + vcomp] = ftf(vreg[j].z);
                VsF[(bb + 12) * 4 + vcomp] = ftf(vreg[j].w);
            }
        }
        __syncthreads();
        // ---- prefetch next tile ----
        if (kt + 1 < nkt) {
            const int nb = (kt + 1) * 64;
#pragma unroll
            for (int j = 0; j < 4; j++) {
                kreg[j] = *(const float4*)&kbase[(size_t)(nb + krow0 + 16 * j) * D_MODEL + kcol4 * 4];
                vreg[j] = *(const float4*)&vbase[(size_t)(nb + vrow) * D_MODEL + (vcol40 + 4 * j) * 4];
            }
        }

        const float4* KsP = (const float4*)(sm + p * 4096);
        const float4* VsP = (const float4*)(sm + 8192 + p * 4096);

        // ---- GEMM1: S[16 x 64] ----
        float sacc[8][4];
#pragma unroll
        for (int i = 0; i < 8; i++)
#pragma unroll
            for (int j = 0; j < 4; j++) sacc[i][j] = 0.f;

#pragma unroll
        for (int ksp = 0; ksp < 4; ksp++) {
            int slot = (lane & 28) | ((lane & 3) ^ ksp);
            float4 kb[8];
#pragma unroll
            for (int nt = 0; nt < 8; nt++)
                kb[nt] = KsP[(ksp * 8 + nt) * 32 + slot];
#pragma unroll
            for (int kh = 0; kh < 2; kh++) {
                const float* a = qfrag[ksp * 2 + kh];
#pragma unroll
                for (int nt = 0; nt < 8; nt++) {
                    float bfr[2];
                    if (kh == 0) { bfr[0] = kb[nt].x; bfr[1] = kb[nt].y; }
                    else         { bfr[0] = kb[nt].z; bfr[1] = kb[nt].w; }
                    mma8(sacc[nt], a, bfr);
                }
            }
        }

        // ---- P = (S/64)^2 * causal, shuffle-transpose, GEMM2 ----
#pragma unroll
        for (int cp = 0; cp < 4; cp++) {
            float4 vb[8];
#pragma unroll
            for (int dn = 0; dn < 8; dn++)
                vb[dn] = VsP[(cp * 8 + dn) * 32 + lane];
#pragma unroll
            for (int kh = 0; kh < 2; kh++) {
                int c = cp * 2 + kh;
                int kc = ktb + c * 8 + 2 * t;
                float s0 = sacc[c][0] * inv64; s0 *= s0; if (kc > qr0)     s0 = 0.f;
                float s1 = sacc[c][1] * inv64; s1 *= s1; if (kc + 1 > qr0) s1 = 0.f;
                float s2 = sacc[c][2] * inv64; s2 *= s2; if (kc > qr1)     s2 = 0.f;
                float s3 = sacc[c][3] * inv64; s3 *= s3; if (kc + 1 > qr1) s3 = 0.f;
                int srcA = (lane & ~3) | (t >> 1);
                int srcB = srcA + 2;
                float u0 = __shfl_sync(0xffffffffu, s0, srcA);
                float u1 = __shfl_sync(0xffffffffu, s1, srcA);
                float u2 = __shfl_sync(0xffffffffu, s2, srcA);
                float u3 = __shfl_sync(0xffffffffu, s3, srcA);
                float v0 = __shfl_sync(0xffffffffu, s0, srcB);
                float v1 = __shfl_sync(0xffffffffu, s1, srcB);
                float v2 = __shfl_sync(0xffffffffu, s2, srcB);
                float v3 = __shfl_sync(0xffffffffu, s3, srcB);
                bool odd = (t & 1);
                float af[4];
                af[0] = ftf(odd ? u1 : u0);   // P(g,   t)
                af[1] = ftf(odd ? u3 : u2);   // P(g+8, t)
                af[2] = ftf(odd ? v1 : v0);   // P(g,   t+4)
                af[3] = ftf(odd ? v3 : v2);   // P(g+8, t+4)
#pragma unroll
                for (int dn = 0; dn < 8; dn++) {
                    float bfr[2];
                    if (kh == 0) { bfr[0] = vb[dn].x; bfr[1] = vb[dn].y; }
                    else         { bfr[0] = vb[dn].z; bfr[1] = vb[dn].w; }
                    mma8(zacc[dn], af, bfr);
                }
            }
        }
        p ^= 1;
    }

    // ---- write Z ----
#pragma unroll
    for (int dn = 0; dn < 8; dn++) {
        int col = dn * 8 + 2 * t;
        *(float2*)&Z[base + (size_t)qr0 * D_MODEL + col] =
            make_float2(zacc[dn][0], zacc[dn][1]);
        *(float2*)&Z[base + (size_t)qr1 * D_MODEL + col] =
            make_float2(zacc[dn][2], zacc[dn][3]);
    }
}

// ---------------- launch ----------------
extern "C" void kernel_launch(void* const* d_in, const int* in_sizes, int n_in,
                              void* d_out, int out_size)
{
    const float* x  = (const float*)d_in[0];
    const float* Wq = (const float*)d_in[1];
    const float* bq = (const float*)d_in[2];
    const float* Wk = (const float*)d_in[3];
    const float* bk = (const float*)d_in[4];
    const float* Wv = (const float*)d_in[5];
    const float* bv = (const float*)d_in[6];
    const float* Wo = (const float*)d_in[7];
    const float* nw = (const float*)d_in[8];
    float* out = (float*)d_out;

    float *q, *k, *v, *z;
    cudaGetSymbolAddress((void**)&q, g_q);
    cudaGetSymbolAddress((void**)&k, g_k);
    cudaGetSymbolAddress((void**)&v, g_v);
    cudaGetSymbolAddress((void**)&z, g_z);

    cudaFuncSetAttribute(gemm_tc_kernel, cudaFuncAttributeMaxDynamicSharedMemorySize, 65536);
    cudaFuncSetAttribute(attn_tc_kernel, cudaFuncAttributeMaxDynamicSharedMemorySize, ATTN_SMEM);

    rope_cache_kernel<<<64, 1024>>>();

    // QKV projections: one launch, 3 jobs
    GemmJobs jq;
    jq.W[0] = Wq; jq.W[1] = Wk; jq.W[2] = Wv;
    jq.bias[0] = bq; jq.bias[1] = bk; jq.bias[2] = bv;
    jq.res[0] = nullptr; jq.res[1] = nullptr; jq.res[2] = nullptr;
    jq.out[0] = q; jq.out[1] = k; jq.out[2] = v;
    gemm_tc_kernel<<<dim3(D_MODEL / 128, MTOT / 128, 3), 256, 65536>>>(x, jq, MTOT, D_MODEL, D_MODEL);

    norm_rope_kernel<<<16384, 256>>>(q, k, nw);

    attn_tc_kernel<<<dim3(16, 32), 256, ATTN_SMEM>>>(q, k, v, z);

    // output projection + residual
    GemmJobs jo;
    jo.W[0] = Wo; jo.W[1] = nullptr; jo.W[2] = nullptr;
    jo.bias[0] = nullptr; jo.bias[1] = nullptr; jo.bias[2] = nullptr;
    jo.res[0] = x; jo.res[1] = nullptr; jo.res[2] = nullptr;
    jo.out[0] = out; jo.out[1] = nullptr; jo.out[2] = nullptr;
    gemm_tc_kernel<<<dim3(D_MODEL / 128, MTOT / 128, 1), 256, 65536>>>(z, jo, MTOT, D_MODEL, D_MODEL);
}

// round 6
// speedup vs baseline: 1.1494x; 1.1494x over previous
#include <cuda_runtime.h>
#include <math.h>
#include <stdint.h>

#define D_MODEL 1024
#define N_HEAD  16
#define D_HEAD  64
#define N_CTX   2048
#define BATCH   2
#define MTOT    (BATCH * N_CTX)   /* 4096 rows */

// ---------------- scratch ----------------
__device__ float g_q[MTOT * D_MODEL];
__device__ float g_k[MTOT * D_MODEL];
__device__ float g_v[MTOT * D_MODEL];
__device__ float g_z[MTOT * D_MODEL];
__device__ float g_cos[N_CTX * 32];
__device__ float g_sin[N_CTX * 32];

// ---------------- helpers ----------------
__device__ __forceinline__ float ftf(float x) {
    uint32_t u;
    asm("cvt.rna.tf32.f32 %0, %1;" : "=r"(u) : "f"(x));
    return __uint_as_float(u);
}

__device__ __forceinline__ void mma8(float c[4], const float a[4], const float b[2]) {
    asm volatile(
        "mma.sync.aligned.m16n8k8.row.col.f32.tf32.tf32.f32 "
        "{%0,%1,%2,%3}, {%4,%5,%6,%7}, {%8,%9}, {%0,%1,%2,%3};\n"
        : "+f"(c[0]), "+f"(c[1]), "+f"(c[2]), "+f"(c[3])
        : "r"(__float_as_uint(a[0])), "r"(__float_as_uint(a[1])),
          "r"(__float_as_uint(a[2])), "r"(__float_as_uint(a[3])),
          "r"(__float_as_uint(b[0])), "r"(__float_as_uint(b[1])));
}

// ---------------- RoPE table ----------------
__global__ void rope_cache_kernel() {
    int i = blockIdx.x * blockDim.x + threadIdx.x;
    int t = i >> 5;
    int j = i & 31;
    float invf = (float)pow(10000.0, -(double)j / 32.0);
    double ang = (double)t * (double)invf;
    double sv, cv;
    sincos(ang, &sv, &cv);
    g_cos[i] = (float)cv;
    g_sin[i] = (float)sv;
}

// ---------------- TF32 GEMM (R3 proven core), multi-job ----------------
struct GemmJobs {
    const float* W[3];
    const float* bias[3];
    const float* res[3];
    float*       out[3];
};

__global__ __launch_bounds__(256, 2)
void gemm_tc_kernel(const float* __restrict__ A, GemmJobs jobs, int M, int N, int K)
{
    __shared__ __align__(16) float As[4096];   // [ks4][mt8][lane32][slot4]
    __shared__ __align__(16) float Bs[4096];   // [ksp2][nt16][lane32][slot4]
    float4* As4 = (float4*)As;
    float4* Bs4 = (float4*)Bs;

    const int z = blockIdx.z;
    const float* W    = jobs.W[z];
    const float* bias = jobs.bias[z];
    const float* res  = jobs.res[z];
    float*       C    = jobs.out[z];

    const int tid = threadIdx.x;
    const int lane = tid & 31;
    const int wid = tid >> 5;
    const int wm = wid & 3, wn = wid >> 2;
    const int m0 = blockIdx.y * 128, n0 = blockIdx.x * 128;

    const int amt = tid >> 5, ag = (tid >> 2) & 7, aks = tid & 3;
    const float* Ap = A + (size_t)(m0 + amt * 16 + ag) * K + aks * 8;
    const int bnt = ((tid >> 5) << 1) | (tid & 1);
    const int bg = (tid >> 2) & 7;
    const int bksp = (tid >> 1) & 1;
    const int bxor = bksp | ((bnt & 1) << 1);
    const float* Wp = W + (size_t)(n0 + bnt * 8 + bg) * K + bksp * 16;

    float acc[2][8][4];
#pragma unroll
    for (int mi = 0; mi < 2; mi++)
#pragma unroll
        for (int ni = 0; ni < 8; ni++)
#pragma unroll
            for (int e = 0; e < 4; e++) acc[mi][ni][e] = 0.f;

    for (int kt = 0; kt < K; kt += 32) {
        float a0[4], a1[4], a2[4], a3[4];
        float w0[4], w1[4], w2[4], w3[4];
        {
            float4 v0 = *(const float4*)(Ap + kt);
            float4 v1 = *(const float4*)(Ap + kt + 4);
            float4 v2 = *(const float4*)(Ap + kt + (size_t)8 * K);
            float4 v3 = *(const float4*)(Ap + kt + (size_t)8 * K + 4);
            a0[0]=v0.x;a0[1]=v0.y;a0[2]=v0.z;a0[3]=v0.w;
            a1[0]=v1.x;a1[1]=v1.y;a1[2]=v1.z;a1[3]=v1.w;
            a2[0]=v2.x;a2[1]=v2.y;a2[2]=v2.z;a2[3]=v2.w;
            a3[0]=v3.x;a3[1]=v3.y;a3[2]=v3.z;a3[3]=v3.w;
            float4 u0 = *(const float4*)(Wp + kt);
            float4 u1 = *(const float4*)(Wp + kt + 4);
            float4 u2 = *(const float4*)(Wp + kt + 8);
            float4 u3 = *(const float4*)(Wp + kt + 12);
            w0[0]=u0.x;w0[1]=u0.y;w0[2]=u0.z;w0[3]=u0.w;
            w1[0]=u1.x;w1[1]=u1.y;w1[2]=u1.z;w1[3]=u1.w;
            w2[0]=u2.x;w2[1]=u2.y;w2[2]=u2.z;w2[3]=u2.w;
            w3[0]=u3.x;w3[1]=u3.y;w3[2]=u3.z;w3[3]=u3.w;
        }
        __syncthreads();
#pragma unroll
        for (int t = 0; t < 4; t++) {
            As4[(aks * 8 + amt) * 32 + ag * 4 + (t ^ aks)] =
                make_float4(ftf(a0[t]), ftf(a2[t]), ftf(a1[t]), ftf(a3[t]));
            Bs4[(bksp * 16 + bnt) * 32 + bg * 4 + (t ^ bxor)] =
                make_float4(ftf(w0[t]), ftf(w1[t]), ftf(w2[t]), ftf(w3[t]));
        }
        __syncthreads();
#pragma unroll
        for (int ksp = 0; ksp < 2; ksp++) {
            float4 bb[8];
#pragma unroll
            for (int ni = 0; ni < 8; ni++) {
                int nt = wn * 8 + ni;
                int xv = ksp | ((nt & 1) << 1);
                int lp = (lane & ~3) | ((lane & 3) ^ xv);
                bb[ni] = Bs4[(ksp * 16 + nt) * 32 + lp];
            }
#pragma unroll
            for (int kh = 0; kh < 2; kh++) {
                int ks = ksp * 2 + kh;
                int lpa = (lane & ~3) | ((lane & 3) ^ ks);
                float a[2][4];
#pragma unroll
                for (int mi = 0; mi < 2; mi++) {
                    float4 aa = As4[(ks * 8 + wm * 2 + mi) * 32 + lpa];
                    a[mi][0] = aa.x; a[mi][1] = aa.y; a[mi][2] = aa.z; a[mi][3] = aa.w;
                }
#pragma unroll
                for (int mi = 0; mi < 2; mi++)
#pragma unroll
                    for (int ni = 0; ni < 8; ni++) {
                        float b[2];
                        if (kh == 0) { b[0] = bb[ni].x; b[1] = bb[ni].y; }
                        else         { b[0] = bb[ni].z; b[1] = bb[ni].w; }
                        mma8(acc[mi][ni], a[mi], b);
                    }
            }
        }
    }

    const int g = lane >> 2, t = lane & 3;
#pragma unroll
    for (int mi = 0; mi < 2; mi++) {
#pragma unroll
        for (int h = 0; h < 2; h++) {
            int m = m0 + wm * 32 + mi * 16 + h * 8 + g;
#pragma unroll
            for (int ni = 0; ni < 8; ni++) {
                int n = n0 + wn * 64 + ni * 8 + 2 * t;
                float2 v = make_float2(acc[mi][ni][h * 2 + 0], acc[mi][ni][h * 2 + 1]);
                if (bias) { v.x += bias[n]; v.y += bias[n + 1]; }
                if (res) {
                    float2 r = *(const float2*)&res[(size_t)m * N + n];
                    v.x += r.x; v.y += r.y;
                }
                *(float2*)&C[(size_t)m * N + n] = v;
            }
        }
    }
}

// ---------------- fused RMSNorm + RoPE ----------------
__global__ __launch_bounds__(256)
void norm_rope_kernel(float* __restrict__ q, float* __restrict__ k,
                      const float* __restrict__ w)
{
    int gw = (blockIdx.x * blockDim.x + threadIdx.x) >> 5;
    int lane = threadIdx.x & 31;
    int which = gw & 1;
    int row = gw >> 1;
    float* ptr = which ? k : q;

    size_t base = (size_t)(row >> 4) * D_MODEL + (size_t)(row & 15) * 64;
    int s = (row >> 4) & (N_CTX - 1);

    float2 xv = *(float2*)&ptr[base + lane * 2];
    float ss = xv.x * xv.x + xv.y * xv.y;
#pragma unroll
    for (int o = 16; o; o >>= 1) ss += __shfl_xor_sync(0xffffffffu, ss, o);
    float r = rsqrtf(ss * (1.0f / 64.0f) + 1.1920929e-07f);

    float y0 = xv.x * r * w[lane * 2];
    float y1 = xv.y * r * w[lane * 2 + 1];

    int j0 = (2 * lane) & 31;
    int j1 = (2 * lane + 1) & 31;
    float c0 = g_cos[s * 32 + j0], s0 = g_sin[s * 32 + j0];
    float c1 = g_cos[s * 32 + j1], s1 = g_sin[s * 32 + j1];

    float2 o;
    o.x = y0 * c0 - y1 * s0;
    o.y = y1 * c1 + y0 * s1;
    *(float2*)&ptr[base + lane * 2] = o;
}

// ---------------- fused quadratic causal attention, TF32 mma ----------------
// CTA: 128 threads (4 warps), q-tile 64 (warp owns 16 q-rows x full 64-k width).
// Single 32KB K/V buffer; 2-3 CTAs co-resident per SM cover barrier/LDG latency.
#define ATTN_SMEM (8192 * 4)   /* 32768 B: Ks 4096 f + Vs 4096 f */

__global__ __launch_bounds__(128)
void attn_tc_kernel(const float* __restrict__ Q, const float* __restrict__ Kg,
                    const float* __restrict__ V, float* __restrict__ Z)
{
    extern __shared__ float sm[];
    float* KsF = sm;            // frag-major K, 16KB
    float* VsF = sm + 4096;     // frag-major V, 16KB

    const int tid = threadIdx.x;
    const int lane = tid & 31;
    const int wp = tid >> 5;                 // warp 0..3
    const int g = lane >> 2, t = lane & 3;
    const int bh = blockIdx.y;
    const int b = bh >> 4, h = bh & 15;
    const int jt = (int)gridDim.x - 1 - (int)blockIdx.x;   // big tiles first
    const size_t base = (size_t)(b * N_CTX) * D_MODEL + h * 64;
    const int nkt = jt + 1;

    // ---- Q fragments in registers: warp wp covers q rows jt*64 + wp*16 ----
    const int q0 = jt * 64 + wp * 16;
    float qfrag[8][4];
    {
        const float* qp  = Q + base + (size_t)(q0 + g) * D_MODEL;
        const float* qp8 = qp + (size_t)8 * D_MODEL;
#pragma unroll
        for (int ks = 0; ks < 8; ks++) {
            qfrag[ks][0] = ftf(qp[ks * 8 + t]);
            qfrag[ks][1] = ftf(qp8[ks * 8 + t]);
            qfrag[ks][2] = ftf(qp[ks * 8 + t + 4]);
            qfrag[ks][3] = ftf(qp8[ks * 8 + t + 4]);
        }
    }

    float zacc[8][4];
#pragma unroll
    for (int i = 0; i < 8; i++)
#pragma unroll
        for (int j = 0; j < 4; j++) zacc[i][j] = 0.f;

    // K loader: thread owns rows krow0+8j (j=0..7), cols kcol4*4..+3
    const int krow0 = tid >> 4, kcol4 = tid & 15;
    const int kksp = kcol4 >> 2, kcomp = kcol4 & 3, kg = krow0 & 7;
    // V loader: thread owns row vrow, cols (vh + 2j)*4..+3
    const int vrow = tid & 63, vh = tid >> 6;
    const int vcp = vrow >> 4, vtt = vrow & 3, vcomp = (vrow >> 2) & 3;
    const int vg0 = vh * 4;
    const int vsw = vtt ^ (vcp & 3);        // bank-fix swizzle

    const float* kbase = Kg + base;
    const float* vbase = V + base;

    const float inv64 = 1.0f / 64.0f;
    const int qr0 = q0 + g;
    const int qr1 = qr0 + 8;

    for (int kt = 0; kt < nkt; ++kt) {
        const int ktb = kt * 64;
        __syncthreads();   // previous iteration's consumers done with buffers
        // ---- K tile -> fragment-major ----
#pragma unroll
        for (int j = 0; j < 8; j++) {
            float4 kv = *(const float4*)&kbase[(size_t)(ktb + krow0 + 8 * j) * D_MODEL + kcol4 * 4];
            int bb = (kksp * 8 + j) * 32 + kg * 4;
            KsF[(bb + (0 ^ kksp)) * 4 + kcomp] = ftf(kv.x);
            KsF[(bb + (1 ^ kksp)) * 4 + kcomp] = ftf(kv.y);
            KsF[(bb + (2 ^ kksp)) * 4 + kcomp] = ftf(kv.z);
            KsF[(bb + (3 ^ kksp)) * 4 + kcomp] = ftf(kv.w);
        }
        // ---- V tile -> fragment-major (cp-xor swizzled) ----
#pragma unroll
        for (int j = 0; j < 8; j++) {
            float4 vv = *(const float4*)&vbase[(size_t)(ktb + vrow) * D_MODEL + (vh + 2 * j) * 4];
            int bb = (vcp * 8 + j) * 32 + vg0 * 4 + vsw;
            VsF[(bb + 0)  * 4 + vcomp] = ftf(vv.x);
            VsF[(bb + 4)  * 4 + vcomp] = ftf(vv.y);
            VsF[(bb + 8)  * 4 + vcomp] = ftf(vv.z);
            VsF[(bb + 12) * 4 + vcomp] = ftf(vv.w);
        }
        __syncthreads();

        const float4* KsP = (const float4*)KsF;
        const float4* VsP = (const float4*)VsF;

        // ---- GEMM1: S[16 x 64] ----
        float sacc[8][4];
#pragma unroll
        for (int i = 0; i < 8; i++)
#pragma unroll
            for (int j = 0; j < 4; j++) sacc[i][j] = 0.f;

#pragma unroll
        for (int ksp = 0; ksp < 4; ksp++) {
            int slot = (lane & 28) | ((lane & 3) ^ ksp);
            float4 kb[8];
#pragma unroll
            for (int nt = 0; nt < 8; nt++)
                kb[nt] = KsP[(ksp * 8 + nt) * 32 + slot];
#pragma unroll
            for (int kh = 0; kh < 2; kh++) {
                const float* a = qfrag[ksp * 2 + kh];
#pragma unroll
                for (int nt = 0; nt < 8; nt++) {
                    float bfr[2];
                    if (kh == 0) { bfr[0] = kb[nt].x; bfr[1] = kb[nt].y; }
                    else         { bfr[0] = kb[nt].z; bfr[1] = kb[nt].w; }
                    mma8(sacc[nt], a, bfr);
                }
            }
        }

        // ---- P = (S/64)^2 * causal, shuffle-transpose, GEMM2 ----
#pragma unroll
        for (int cp = 0; cp < 4; cp++) {
            int vslot = (lane & 28) | ((lane & 3) ^ (cp & 3));
            float4 vb[8];
#pragma unroll
            for (int dn = 0; dn < 8; dn++)
                vb[dn] = VsP[(cp * 8 + dn) * 32 + vslot];
#pragma unroll
            for (int kh = 0; kh < 2; kh++) {
                int c = cp * 2 + kh;
                int kc = ktb + c * 8 + 2 * t;
                float s0 = sacc[c][0] * inv64; s0 *= s0; if (kc > qr0)     s0 = 0.f;
                float s1 = sacc[c][1] * inv64; s1 *= s1; if (kc + 1 > qr0) s1 = 0.f;
                float s2 = sacc[c][2] * inv64; s2 *= s2; if (kc > qr1)     s2 = 0.f;
                float s3 = sacc[c][3] * inv64; s3 *= s3; if (kc + 1 > qr1) s3 = 0.f;
                int srcA = (lane & ~3) | (t >> 1);
                int srcB = srcA + 2;
                float u0 = __shfl_sync(0xffffffffu, s0, srcA);
                float u1 = __shfl_sync(0xffffffffu, s1, srcA);
                float u2 = __shfl_sync(0xffffffffu, s2, srcA);
                float u3 = __shfl_sync(0xffffffffu, s3, srcA);
                float v0 = __shfl_sync(0xffffffffu, s0, srcB);
                float v1 = __shfl_sync(0xffffffffu, s1, srcB);
                float v2 = __shfl_sync(0xffffffffu, s2, srcB);
                float v3 = __shfl_sync(0xffffffffu, s3, srcB);
                bool odd = (t & 1);
                float af[4];
                af[0] = ftf(odd ? u1 : u0);   // P(g,   t)
                af[1] = ftf(odd ? u3 : u2);   // P(g+8, t)
                af[2] = ftf(odd ? v1 : v0);   // P(g,   t+4)
                af[3] = ftf(odd ? v3 : v2);   // P(g+8, t+4)
#pragma unroll
                for (int dn = 0; dn < 8; dn++) {
                    float bfr[2];
                    if (kh == 0) { bfr[0] = vb[dn].x; bfr[1] = vb[dn].y; }
                    else         { bfr[0] = vb[dn].z; bfr[1] = vb[dn].w; }
                    mma8(zacc[dn], af, bfr);
                }
            }
        }
    }

    // ---- write Z ----
#pragma unroll
    for (int dn = 0; dn < 8; dn++) {
        int col = dn * 8 + 2 * t;
        *(float2*)&Z[base + (size_t)qr0 * D_MODEL + col] =
            make_float2(zacc[dn][0], zacc[dn][1]);
        *(float2*)&Z[base + (size_t)qr1 * D_MODEL + col] =
            make_float2(zacc[dn][2], zacc[dn][3]);
    }
}

// ---------------- launch ----------------
extern "C" void kernel_launch(void* const* d_in, const int* in_sizes, int n_in,
                              void* d_out, int out_size)
{
    const float* x  = (const float*)d_in[0];
    const float* Wq = (const float*)d_in[1];
    const float* bq = (const float*)d_in[2];
    const float* Wk = (const float*)d_in[3];
    const float* bk = (const float*)d_in[4];
    const float* Wv = (const float*)d_in[5];
    const float* bv = (const float*)d_in[6];
    const float* Wo = (const float*)d_in[7];
    const float* nw = (const float*)d_in[8];
    float* out = (float*)d_out;

    float *q, *k, *v, *z;
    cudaGetSymbolAddress((void**)&q, g_q);
    cudaGetSymbolAddress((void**)&k, g_k);
    cudaGetSymbolAddress((void**)&v, g_v);
    cudaGetSymbolAddress((void**)&z, g_z);

    cudaFuncSetAttribute(attn_tc_kernel, cudaFuncAttributeMaxDynamicSharedMemorySize, ATTN_SMEM);

    rope_cache_kernel<<<64, 1024>>>();

    // QKV projections: one launch, 3 jobs
    GemmJobs jq;
    jq.W[0] = Wq; jq.W[1] = Wk; jq.W[2] = Wv;
    jq.bias[0] = bq; jq.bias[1] = bk; jq.bias[2] = bv;
    jq.res[0] = nullptr; jq.res[1] = nullptr; jq.res[2] = nullptr;
    jq.out[0] = q; jq.out[1] = k; jq.out[2] = v;
    gemm_tc_kernel<<<dim3(D_MODEL / 128, MTOT / 128, 3), 256>>>(x, jq, MTOT, D_MODEL, D_MODEL);

    norm_rope_kernel<<<16384, 256>>>(q, k, nw);

    attn_tc_kernel<<<dim3(32, 32), 128, ATTN_SMEM>>>(q, k, v, z);

    // output projection + residual
    GemmJobs jo;
    jo.W[0] = Wo; jo.W[1] = nullptr; jo.W[2] = nullptr;
    jo.bias[0] = nullptr; jo.bias[1] = nullptr; jo.bias[2] = nullptr;
    jo.res[0] = x; jo.res[1] = nullptr; jo.res[2] = nullptr;
    jo.out[0] = out; jo.out[1] = nullptr; jo.out[2] = nullptr;
    gemm_tc_kernel<<<dim3(D_MODEL / 128, MTOT / 128, 1), 256>>>(z, jo, MTOT, D_MODEL, D_MODEL);
}

// round 7
// speedup vs baseline: 1.2459x; 1.0839x over previous
#include <cuda_runtime.h>
#include <math.h>
#include <stdint.h>

#define D_MODEL 1024
#define N_HEAD  16
#define D_HEAD  64
#define N_CTX   2048
#define BATCH   2
#define MTOT    (BATCH * N_CTX)   /* 4096 rows */

// ---------------- scratch ----------------
__device__ float g_q[MTOT * D_MODEL];
__device__ float g_k[MTOT * D_MODEL];
__device__ float g_v[MTOT * D_MODEL];
__device__ float g_z[MTOT * D_MODEL];
__device__ float g_cos[N_CTX * 32];
__device__ float g_sin[N_CTX * 32];

// ---------------- helpers ----------------
__device__ __forceinline__ float ftf(float x) {
    uint32_t u;
    asm("cvt.rna.tf32.f32 %0, %1;" : "=r"(u) : "f"(x));
    return __uint_as_float(u);
}

__device__ __forceinline__ void mma8(float c[4], const float a[4], const float b[2]) {
    asm volatile(
        "mma.sync.aligned.m16n8k8.row.col.f32.tf32.tf32.f32 "
        "{%0,%1,%2,%3}, {%4,%5,%6,%7}, {%8,%9}, {%0,%1,%2,%3};\n"
        : "+f"(c[0]), "+f"(c[1]), "+f"(c[2]), "+f"(c[3])
        : "r"(__float_as_uint(a[0])), "r"(__float_as_uint(a[1])),
          "r"(__float_as_uint(a[2])), "r"(__float_as_uint(a[3])),
          "r"(__float_as_uint(b[0])), "r"(__float_as_uint(b[1])));
}

// ---------------- RoPE table ----------------
__global__ void rope_cache_kernel() {
    int i = blockIdx.x * blockDim.x + threadIdx.x;
    int t = i >> 5;
    int j = i & 31;
    float invf = (float)pow(10000.0, -(double)j / 32.0);
    double ang = (double)t * (double)invf;
    double sv, cv;
    sincos(ang, &sv, &cv);
    g_cos[i] = (float)cv;
    g_sin[i] = (float)sv;
}

// ---------------- TF32 GEMM (proven core), multi-job ----------------
struct GemmJobs {
    const float* W[3];
    const float* bias[3];
    const float* res[3];
    float*       out[3];
};

__global__ __launch_bounds__(256, 2)
void gemm_tc_kernel(const float* __restrict__ A, GemmJobs jobs, int M, int N, int K)
{
    __shared__ __align__(16) float As[4096];
    __shared__ __align__(16) float Bs[4096];
    float4* As4 = (float4*)As;
    float4* Bs4 = (float4*)Bs;

    const int z = blockIdx.z;
    const float* W    = jobs.W[z];
    const float* bias = jobs.bias[z];
    const float* res  = jobs.res[z];
    float*       C    = jobs.out[z];

    const int tid = threadIdx.x;
    const int lane = tid & 31;
    const int wid = tid >> 5;
    const int wm = wid & 3, wn = wid >> 2;
    const int m0 = blockIdx.y * 128, n0 = blockIdx.x * 128;

    const int amt = tid >> 5, ag = (tid >> 2) & 7, aks = tid & 3;
    const float* Ap = A + (size_t)(m0 + amt * 16 + ag) * K + aks * 8;
    const int bnt = ((tid >> 5) << 1) | (tid & 1);
    const int bg = (tid >> 2) & 7;
    const int bksp = (tid >> 1) & 1;
    const int bxor = bksp | ((bnt & 1) << 1);
    const float* Wp = W + (size_t)(n0 + bnt * 8 + bg) * K + bksp * 16;

    float acc[2][8][4];
#pragma unroll
    for (int mi = 0; mi < 2; mi++)
#pragma unroll
        for (int ni = 0; ni < 8; ni++)
#pragma unroll
            for (int e = 0; e < 4; e++) acc[mi][ni][e] = 0.f;

    for (int kt = 0; kt < K; kt += 32) {
        float a0[4], a1[4], a2[4], a3[4];
        float w0[4], w1[4], w2[4], w3[4];
        {
            float4 v0 = *(const float4*)(Ap + kt);
            float4 v1 = *(const float4*)(Ap + kt + 4);
            float4 v2 = *(const float4*)(Ap + kt + (size_t)8 * K);
            float4 v3 = *(const float4*)(Ap + kt + (size_t)8 * K + 4);
            a0[0]=v0.x;a0[1]=v0.y;a0[2]=v0.z;a0[3]=v0.w;
            a1[0]=v1.x;a1[1]=v1.y;a1[2]=v1.z;a1[3]=v1.w;
            a2[0]=v2.x;a2[1]=v2.y;a2[2]=v2.z;a2[3]=v2.w;
            a3[0]=v3.x;a3[1]=v3.y;a3[2]=v3.z;a3[3]=v3.w;
            float4 u0 = *(const float4*)(Wp + kt);
            float4 u1 = *(const float4*)(Wp + kt + 4);
            float4 u2 = *(const float4*)(Wp + kt + 8);
            float4 u3 = *(const float4*)(Wp + kt + 12);
            w0[0]=u0.x;w0[1]=u0.y;w0[2]=u0.z;w0[3]=u0.w;
            w1[0]=u1.x;w1[1]=u1.y;w1[2]=u1.z;w1[3]=u1.w;
            w2[0]=u2.x;w2[1]=u2.y;w2[2]=u2.z;w2[3]=u2.w;
            w3[0]=u3.x;w3[1]=u3.y;w3[2]=u3.z;w3[3]=u3.w;
        }
        __syncthreads();
#pragma unroll
        for (int t = 0; t < 4; t++) {
            As4[(aks * 8 + amt) * 32 + ag * 4 + (t ^ aks)] =
                make_float4(ftf(a0[t]), ftf(a2[t]), ftf(a1[t]), ftf(a3[t]));
            Bs4[(bksp * 16 + bnt) * 32 + bg * 4 + (t ^ bxor)] =
                make_float4(ftf(w0[t]), ftf(w1[t]), ftf(w2[t]), ftf(w3[t]));
        }
        __syncthreads();
#pragma unroll
        for (int ksp = 0; ksp < 2; ksp++) {
            float4 bb[8];
#pragma unroll
            for (int ni = 0; ni < 8; ni++) {
                int nt = wn * 8 + ni;
                int xv = ksp | ((nt & 1) << 1);
                int lp = (lane & ~3) | ((lane & 3) ^ xv);
                bb[ni] = Bs4[(ksp * 16 + nt) * 32 + lp];
            }
#pragma unroll
            for (int kh = 0; kh < 2; kh++) {
                int ks = ksp * 2 + kh;
                int lpa = (lane & ~3) | ((lane & 3) ^ ks);
                float a[2][4];
#pragma unroll
                for (int mi = 0; mi < 2; mi++) {
                    float4 aa = As4[(ks * 8 + wm * 2 + mi) * 32 + lpa];
                    a[mi][0] = aa.x; a[mi][1] = aa.y; a[mi][2] = aa.z; a[mi][3] = aa.w;
                }
#pragma unroll
                for (int mi = 0; mi < 2; mi++)
#pragma unroll
                    for (int ni = 0; ni < 8; ni++) {
                        float b[2];
                        if (kh == 0) { b[0] = bb[ni].x; b[1] = bb[ni].y; }
                        else         { b[0] = bb[ni].z; b[1] = bb[ni].w; }
                        mma8(acc[mi][ni], a[mi], b);
                    }
            }
        }
    }

    const int g = lane >> 2, t = lane & 3;
#pragma unroll
    for (int mi = 0; mi < 2; mi++) {
#pragma unroll
        for (int h = 0; h < 2; h++) {
            int m = m0 + wm * 32 + mi * 16 + h * 8 + g;
#pragma unroll
            for (int ni = 0; ni < 8; ni++) {
                int n = n0 + wn * 64 + ni * 8 + 2 * t;
                float2 v = make_float2(acc[mi][ni][h * 2 + 0], acc[mi][ni][h * 2 + 1]);
                if (bias) { v.x += bias[n]; v.y += bias[n + 1]; }
                if (res) {
                    float2 r = *(const float2*)&res[(size_t)m * N + n];
                    v.x += r.x; v.y += r.y;
                }
                *(float2*)&C[(size_t)m * N + n] = v;
            }
        }
    }
}

// ---------------- fused RMSNorm + RoPE ----------------
__global__ __launch_bounds__(256)
void norm_rope_kernel(float* __restrict__ q, float* __restrict__ k,
                      const float* __restrict__ w)
{
    int gw = (blockIdx.x * blockDim.x + threadIdx.x) >> 5;
    int lane = threadIdx.x & 31;
    int which = gw & 1;
    int row = gw >> 1;
    float* ptr = which ? k : q;

    size_t base = (size_t)(row >> 4) * D_MODEL + (size_t)(row & 15) * 64;
    int s = (row >> 4) & (N_CTX - 1);

    float2 xv = *(float2*)&ptr[base + lane * 2];
    float ss = xv.x * xv.x + xv.y * xv.y;
#pragma unroll
    for (int o = 16; o; o >>= 1) ss += __shfl_xor_sync(0xffffffffu, ss, o);
    float r = rsqrtf(ss * (1.0f / 64.0f) + 1.1920929e-07f);

    float y0 = xv.x * r * w[lane * 2];
    float y1 = xv.y * r * w[lane * 2 + 1];

    int j0 = (2 * lane) & 31;
    int j1 = (2 * lane + 1) & 31;
    float c0 = g_cos[s * 32 + j0], s0 = g_sin[s * 32 + j0];
    float c1 = g_cos[s * 32 + j1], s1 = g_sin[s * 32 + j1];

    float2 o;
    o.x = y0 * c0 - y1 * s0;
    o.y = y1 * c1 + y0 * s1;
    *(float2*)&ptr[base + lane * 2] = o;
}

// ---------------- fused quadratic causal attention, TF32 mma ----------------
// CTA: 128 threads (4 warps), q-tile 128; each warp owns 32 q-rows x full 64-k.
// Q tile in smem fragment-major (loaded once); K/V per k-tile; 2 CTAs/SM.
#define ATTN_SMEM (16384 * 4)   /* 64 KB: Qs 32KB | Ks 16KB | Vs 16KB */

__global__ __launch_bounds__(128)
void attn_tc_kernel(const float* __restrict__ Q, const float* __restrict__ Kg,
                    const float* __restrict__ V, float* __restrict__ Z)
{
    extern __shared__ float sm[];
    float4* Qs4 = (float4*)sm;        // [ks8][mt8][lane32] float4 frags
    float*  KsF = sm + 8192;          // frag-major K
    float*  VsF = sm + 12288;         // frag-major V

    const int tid = threadIdx.x;
    const int lane = tid & 31;
    const int wp = tid >> 5;                 // warp 0..3
    const int g = lane >> 2, t = lane & 3;
    const int bh = blockIdx.y;
    const int b = bh >> 4, h = bh & 15;
    const int jt = (int)gridDim.x - 1 - (int)blockIdx.x;   // big tiles first
    const size_t base = (size_t)(b * N_CTX) * D_MODEL + h * 64;
    const int nkt = 2 * jt + 2;

    // ---- Q tile (128 x 64) -> fragment-major smem, once ----
    {
        const int r0 = tid >> 4, c4 = tid & 15;
        const int qks = c4 >> 1, th = c4 & 1;
        const int kx = qks & 3;
#pragma unroll
        for (int j = 0; j < 16; j++) {
            int r = 8 * j + r0;
            int mt = r >> 4, gg = r & 15;
            int comp = (gg >> 3) + 2 * th;
            int gq = gg & 7;
            float4 qv = *(const float4*)&Q[base + (size_t)(jt * 128 + r) * D_MODEL + c4 * 4];
            float vals[4] = {qv.x, qv.y, qv.z, qv.w};
            float* dst = (float*)Qs4 + ((qks * 8 + mt) * 32) * 4 + comp;
#pragma unroll
            for (int i = 0; i < 4; i++)
                dst[(4 * gq + (i ^ kx)) * 4] = ftf(vals[i]);
        }
    }

    float zacc[2][8][4];
#pragma unroll
    for (int mm = 0; mm < 2; mm++)
#pragma unroll
        for (int i = 0; i < 8; i++)
#pragma unroll
            for (int j = 0; j < 4; j++) zacc[mm][i][j] = 0.f;

    // K loader: rows krow0+8j, cols kcol4*4..+3
    const int krow0 = tid >> 4, kcol4 = tid & 15;
    const int kksp = kcol4 >> 2, kcomp = kcol4 & 3;
    // V loader: row vrow, cols (vh + 2j)*4..+3
    const int vrow = tid & 63, vh = tid >> 6;
    const int vcp = vrow >> 4, vtt = vrow & 3, vcomp = (vrow >> 2) & 3;
    const int vg0 = vh * 4;
    const int vsw = vtt ^ (vcp & 3);

    const float* kbase = Kg + base;
    const float* vbase = V + base;

    const float inv64 = 1.0f / 64.0f;
    const int qbase = jt * 128 + wp * 32;

    for (int kt = 0; kt < nkt; ++kt) {
        const int ktb = kt * 64;
        __syncthreads();   // previous iteration's consumers done (covers Q store at kt=0)
        // ---- K tile -> fragment-major ----
#pragma unroll
        for (int j = 0; j < 8; j++) {
            float4 kv = *(const float4*)&kbase[(size_t)(ktb + krow0 + 8 * j) * D_MODEL + kcol4 * 4];
            int bb = (kksp * 8 + j) * 32 + krow0 * 4;
            KsF[(bb + (0 ^ kksp)) * 4 + kcomp] = ftf(kv.x);
            KsF[(bb + (1 ^ kksp)) * 4 + kcomp] = ftf(kv.y);
            KsF[(bb + (2 ^ kksp)) * 4 + kcomp] = ftf(kv.z);
            KsF[(bb + (3 ^ kksp)) * 4 + kcomp] = ftf(kv.w);
        }
        // ---- V tile -> fragment-major (cp-xor swizzled) ----
#pragma unroll
        for (int j = 0; j < 8; j++) {
            float4 vv = *(const float4*)&vbase[(size_t)(ktb + vrow) * D_MODEL + (vh + 2 * j) * 4];
            int bb = (vcp * 8 + j) * 32 + vg0 * 4 + vsw;
            VsF[(bb + 0)  * 4 + vcomp] = ftf(vv.x);
            VsF[(bb + 4)  * 4 + vcomp] = ftf(vv.y);
            VsF[(bb + 8)  * 4 + vcomp] = ftf(vv.z);
            VsF[(bb + 12) * 4 + vcomp] = ftf(vv.w);
        }
        __syncthreads();

        const float4* KsP = (const float4*)KsF;
        const float4* VsP = (const float4*)VsF;

        // ---- GEMM1: S[32 x 64] per warp ----
        float sacc[2][8][4];
#pragma unroll
        for (int mm = 0; mm < 2; mm++)
#pragma unroll
            for (int i = 0; i < 8; i++)
#pragma unroll
                for (int j = 0; j < 4; j++) sacc[mm][i][j] = 0.f;

#pragma unroll
        for (int ksp = 0; ksp < 4; ksp++) {
            int slot = (lane & 28) | ((lane & 3) ^ ksp);
            float4 kb[8];
#pragma unroll
            for (int nt = 0; nt < 8; nt++)
                kb[nt] = KsP[(ksp * 8 + nt) * 32 + slot];
#pragma unroll
            for (int kh = 0; kh < 2; kh++) {
                int ks = ksp * 2 + kh;
                int qslot = (lane & 28) | ((lane & 3) ^ (ks & 3));
                float4 qa0 = Qs4[(ks * 8 + wp * 2 + 0) * 32 + qslot];
                float4 qa1 = Qs4[(ks * 8 + wp * 2 + 1) * 32 + qslot];
                float a0[4] = {qa0.x, qa0.y, qa0.z, qa0.w};
                float a1[4] = {qa1.x, qa1.y, qa1.z, qa1.w};
#pragma unroll
                for (int nt = 0; nt < 8; nt++) {
                    float bfr[2];
                    if (kh == 0) { bfr[0] = kb[nt].x; bfr[1] = kb[nt].y; }
                    else         { bfr[0] = kb[nt].z; bfr[1] = kb[nt].w; }
                    mma8(sacc[0][nt], a0, bfr);
                    mma8(sacc[1][nt], a1, bfr);
                }
            }
        }

        // ---- P = (S/64)^2 * causal, shuffle-transpose, GEMM2 ----
#pragma unroll
        for (int cp = 0; cp < 4; cp++) {
            int vslot = (lane & 28) | ((lane & 3) ^ (cp & 3));
            float4 vb[8];
#pragma unroll
            for (int dn = 0; dn < 8; dn++)
                vb[dn] = VsP[(cp * 8 + dn) * 32 + vslot];
#pragma unroll
            for (int kh = 0; kh < 2; kh++) {
                int c = cp * 2 + kh;
                int kc = ktb + c * 8 + 2 * t;
                int srcA = (lane & ~3) | (t >> 1);
                int srcB = srcA + 2;
                bool odd = (t & 1);
#pragma unroll
                for (int mm = 0; mm < 2; mm++) {
                    int qr0 = qbase + mm * 16 + g;
                    int qr1 = qr0 + 8;
                    float s0 = sacc[mm][c][0] * inv64; s0 *= s0; if (kc > qr0)     s0 = 0.f;
                    float s1 = sacc[mm][c][1] * inv64; s1 *= s1; if (kc + 1 > qr0) s1 = 0.f;
                    float s2 = sacc[mm][c][2] * inv64; s2 *= s2; if (kc > qr1)     s2 = 0.f;
                    float s3 = sacc[mm][c][3] * inv64; s3 *= s3; if (kc + 1 > qr1) s3 = 0.f;
                    float u0 = __shfl_sync(0xffffffffu, s0, srcA);
                    float u1 = __shfl_sync(0xffffffffu, s1, srcA);
                    float u2 = __shfl_sync(0xffffffffu, s2, srcA);
                    float u3 = __shfl_sync(0xffffffffu, s3, srcA);
                    float v0 = __shfl_sync(0xffffffffu, s0, srcB);
                    float v1 = __shfl_sync(0xffffffffu, s1, srcB);
                    float v2 = __shfl_sync(0xffffffffu, s2, srcB);
                    float v3 = __shfl_sync(0xffffffffu, s3, srcB);
                    float af[4];
                    af[0] = ftf(odd ? u1 : u0);   // P(g,   t)
                    af[1] = ftf(odd ? u3 : u2);   // P(g+8, t)
                    af[2] = ftf(odd ? v1 : v0);   // P(g,   t+4)
                    af[3] = ftf(odd ? v3 : v2);   // P(g+8, t+4)
#pragma unroll
                    for (int dn = 0; dn < 8; dn++) {
                        float bfr[2];
                        if (kh == 0) { bfr[0] = vb[dn].x; bfr[1] = vb[dn].y; }
                        else         { bfr[0] = vb[dn].z; bfr[1] = vb[dn].w; }
                        mma8(zacc[mm][dn], af, bfr);
                    }
                }
            }
        }
    }

    // ---- write Z ----
#pragma unroll
    for (int mm = 0; mm < 2; mm++) {
        int qr0 = qbase + mm * 16 + g;
        int qr1 = qr0 + 8;
#pragma unroll
        for (int dn = 0; dn < 8; dn++) {
            int col = dn * 8 + 2 * t;
            *(float2*)&Z[base + (size_t)qr0 * D_MODEL + col] =
                make_float2(zacc[mm][dn][0], zacc[mm][dn][1]);
            *(float2*)&Z[base + (size_t)qr1 * D_MODEL + col] =
                make_float2(zacc[mm][dn][2], zacc[mm][dn][3]);
        }
    }
}

// ---------------- launch ----------------
extern "C" void kernel_launch(void* const* d_in, const int* in_sizes, int n_in,
                              void* d_out, int out_size)
{
    const float* x  = (const float*)d_in[0];
    const float* Wq = (const float*)d_in[1];
    const float* bq = (const float*)d_in[2];
    const float* Wk = (const float*)d_in[3];
    const float* bk = (const float*)d_in[4];
    const float* Wv = (const float*)d_in[5];
    const float* bv = (const float*)d_in[6];
    const float* Wo = (const float*)d_in[7];
    const float* nw = (const float*)d_in[8];
    float* out = (float*)d_out;

    float *q, *k, *v, *z;
    cudaGetSymbolAddress((void**)&q, g_q);
    cudaGetSymbolAddress((void**)&k, g_k);
    cudaGetSymbolAddress((void**)&v, g_v);
    cudaGetSymbolAddress((void**)&z, g_z);

    cudaFuncSetAttribute(attn_tc_kernel, cudaFuncAttributeMaxDynamicSharedMemorySize, ATTN_SMEM);

    rope_cache_kernel<<<64, 1024>>>();

    GemmJobs jq;
    jq.W[0] = Wq; jq.W[1] = Wk; jq.W[2] = Wv;
    jq.bias[0] = bq; jq.bias[1] = bk; jq.bias[2] = bv;
    jq.res[0] = nullptr; jq.res[1] = nullptr; jq.res[2] = nullptr;
    jq.out[0] = q; jq.out[1] = k; jq.out[2] = v;
    gemm_tc_kernel<<<dim3(D_MODEL / 128, MTOT / 128, 3), 256>>>(x, jq, MTOT, D_MODEL, D_MODEL);

    norm_rope_kernel<<<16384, 256>>>(q, k, nw);

    attn_tc_kernel<<<dim3(16, 32), 128, ATTN_SMEM>>>(q, k, v, z);

    GemmJobs jo;
    jo.W[0] = Wo; jo.W[1] = nullptr; jo.W[2] = nullptr;
    jo.bias[0] = nullptr; jo.bias[1] = nullptr; jo.bias[2] = nullptr;
    jo.res[0] = x; jo.res[1] = nullptr; jo.res[2] = nullptr;
    jo.out[0] = out; jo.out[1] = nullptr; jo.out[2] = nullptr;
    gemm_tc_kernel<<<dim3(D_MODEL / 128, MTOT / 128, 1), 256>>>(z, jo, MTOT, D_MODEL, D_MODEL);
}

// round 9
// speedup vs baseline: 1.3098x; 1.0513x over previous
#include <cuda_runtime.h>
#include <math.h>
#include <stdint.h>

#define D_MODEL 1024
#define N_HEAD  16
#define D_HEAD  64
#define N_CTX   2048
#define BATCH   2
#define MTOT    (BATCH * N_CTX)   /* 4096 rows */

// ---------------- scratch ----------------
__device__ float g_q[MTOT * D_MODEL];
__device__ float g_k[MTOT * D_MODEL];
__device__ float g_v[MTOT * D_MODEL];
__device__ float g_z[MTOT * D_MODEL];
__device__ float g_cos[N_CTX * 32];
__device__ float g_sin[N_CTX * 32];

// ---------------- helpers ----------------
__device__ __forceinline__ float ftf(float x) {
    uint32_t u;
    asm("cvt.rna.tf32.f32 %0, %1;" : "=r"(u) : "f"(x));
    return __uint_as_float(u);
}

__device__ __forceinline__ void mma8(float c[4], const float a[4], const float b[2]) {
    asm volatile(
        "mma.sync.aligned.m16n8k8.row.col.f32.tf32.tf32.f32 "
        "{%0,%1,%2,%3}, {%4,%5,%6,%7}, {%8,%9}, {%0,%1,%2,%3};\n"
        : "+f"(c[0]), "+f"(c[1]), "+f"(c[2]), "+f"(c[3])
        : "r"(__float_as_uint(a[0])), "r"(__float_as_uint(a[1])),
          "r"(__float_as_uint(a[2])), "r"(__float_as_uint(a[3])),
          "r"(__float_as_uint(b[0])), "r"(__float_as_uint(b[1])));
}

// ---------------- RoPE table ----------------
__global__ void rope_cache_kernel() {
    int i = blockIdx.x * blockDim.x + threadIdx.x;
    int t = i >> 5;
    int j = i & 31;
    float invf = (float)pow(10000.0, -(double)j / 32.0);
    double ang = (double)t * (double)invf;
    double sv, cv;
    sincos(ang, &sv, &cv);
    g_cos[i] = (float)cv;
    g_sin[i] = (float)sv;
}

// ---------------- TF32 GEMM (proven core), multi-job ----------------
struct GemmJobs {
    const float* W[3];
    const float* bias[3];
    const float* res[3];
    float*       out[3];
};

__global__ __launch_bounds__(256, 2)
void gemm_tc_kernel(const float* __restrict__ A, GemmJobs jobs, int M, int N, int K)
{
    __shared__ __align__(16) float As[4096];
    __shared__ __align__(16) float Bs[4096];
    float4* As4 = (float4*)As;
    float4* Bs4 = (float4*)Bs;

    const int z = blockIdx.z;
    const float* W    = jobs.W[z];
    const float* bias = jobs.bias[z];
    const float* res  = jobs.res[z];
    float*       C    = jobs.out[z];

    const int tid = threadIdx.x;
    const int lane = tid & 31;
    const int wid = tid >> 5;
    const int wm = wid & 3, wn = wid >> 2;
    const int m0 = blockIdx.y * 128, n0 = blockIdx.x * 128;

    const int amt = tid >> 5, ag = (tid >> 2) & 7, aks = tid & 3;
    const float* Ap = A + (size_t)(m0 + amt * 16 + ag) * K + aks * 8;
    const int bnt = ((tid >> 5) << 1) | (tid & 1);
    const int bg = (tid >> 2) & 7;
    const int bksp = (tid >> 1) & 1;
    const int bxor = bksp | ((bnt & 1) << 1);
    const float* Wp = W + (size_t)(n0 + bnt * 8 + bg) * K + bksp * 16;

    float acc[2][8][4];
#pragma unroll
    for (int mi = 0; mi < 2; mi++)
#pragma unroll
        for (int ni = 0; ni < 8; ni++)
#pragma unroll
            for (int e = 0; e < 4; e++) acc[mi][ni][e] = 0.f;

    for (int kt = 0; kt < K; kt += 32) {
        float a0[4], a1[4], a2[4], a3[4];
        float w0[4], w1[4], w2[4], w3[4];
        {
            float4 v0 = *(const float4*)(Ap + kt);
            float4 v1 = *(const float4*)(Ap + kt + 4);
            float4 v2 = *(const float4*)(Ap + kt + (size_t)8 * K);
            float4 v3 = *(const float4*)(Ap + kt + (size_t)8 * K + 4);
            a0[0]=v0.x;a0[1]=v0.y;a0[2]=v0.z;a0[3]=v0.w;
            a1[0]=v1.x;a1[1]=v1.y;a1[2]=v1.z;a1[3]=v1.w;
            a2[0]=v2.x;a2[1]=v2.y;a2[2]=v2.z;a2[3]=v2.w;
            a3[0]=v3.x;a3[1]=v3.y;a3[2]=v3.z;a3[3]=v3.w;
            float4 u0 = *(const float4*)(Wp + kt);
            float4 u1 = *(const float4*)(Wp + kt + 4);
            float4 u2 = *(const float4*)(Wp + kt + 8);
            float4 u3 = *(const float4*)(Wp + kt + 12);
            w0[0]=u0.x;w0[1]=u0.y;w0[2]=u0.z;w0[3]=u0.w;
            w1[0]=u1.x;w1[1]=u1.y;w1[2]=u1.z;w1[3]=u1.w;
            w2[0]=u2.x;w2[1]=u2.y;w2[2]=u2.z;w2[3]=u2.w;
            w3[0]=u3.x;w3[1]=u3.y;w3[2]=u3.z;w3[3]=u3.w;
        }
        __syncthreads();
#pragma unroll
        for (int t = 0; t < 4; t++) {
            As4[(aks * 8 + amt) * 32 + ag * 4 + (t ^ aks)] =
                make_float4(ftf(a0[t]), ftf(a2[t]), ftf(a1[t]), ftf(a3[t]));
            Bs4[(bksp * 16 + bnt) * 32 + bg * 4 + (t ^ bxor)] =
                make_float4(ftf(w0[t]), ftf(w1[t]), ftf(w2[t]), ftf(w3[t]));
        }
        __syncthreads();
#pragma unroll
        for (int ksp = 0; ksp < 2; ksp++) {
            float4 bb[8];
#pragma unroll
            for (int ni = 0; ni < 8; ni++) {
                int nt = wn * 8 + ni;
                int xv = ksp | ((nt & 1) << 1);
                int lp = (lane & ~3) | ((lane & 3) ^ xv);
                bb[ni] = Bs4[(ksp * 16 + nt) * 32 + lp];
            }
#pragma unroll
            for (int kh = 0; kh < 2; kh++) {
                int ks = ksp * 2 + kh;
                int lpa = (lane & ~3) | ((lane & 3) ^ ks);
                float a[2][4];
#pragma unroll
                for (int mi = 0; mi < 2; mi++) {
                    float4 aa = As4[(ks * 8 + wm * 2 + mi) * 32 + lpa];
                    a[mi][0] = aa.x; a[mi][1] = aa.y; a[mi][2] = aa.z; a[mi][3] = aa.w;
                }
#pragma unroll
                for (int mi = 0; mi < 2; mi++)
#pragma unroll
                    for (int ni = 0; ni < 8; ni++) {
                        float b[2];
                        if (kh == 0) { b[0] = bb[ni].x; b[1] = bb[ni].y; }
                        else         { b[0] = bb[ni].z; b[1] = bb[ni].w; }
                        mma8(acc[mi][ni], a[mi], b);
                    }
            }
        }
    }

    const int g = lane >> 2, t = lane & 3;
#pragma unroll
    for (int mi = 0; mi < 2; mi++) {
#pragma unroll
        for (int h = 0; h < 2; h++) {
            int m = m0 + wm * 32 + mi * 16 + h * 8 + g;
#pragma unroll
            for (int ni = 0; ni < 8; ni++) {
                int n = n0 + wn * 64 + ni * 8 + 2 * t;
                float2 v = make_float2(acc[mi][ni][h * 2 + 0], acc[mi][ni][h * 2 + 1]);
                if (bias) { v.x += bias[n]; v.y += bias[n + 1]; }
                if (res) {
                    float2 r = *(const float2*)&res[(size_t)m * N + n];
                    v.x += r.x; v.y += r.y;
                }
                *(float2*)&C[(size_t)m * N + n] = v;
            }
        }
    }
}

// ---------------- fused RMSNorm + RoPE ----------------
__global__ __launch_bounds__(256)
void norm_rope_kernel(float* __restrict__ q, float* __restrict__ k,
                      const float* __restrict__ w)
{
    int gw = (blockIdx.x * blockDim.x + threadIdx.x) >> 5;
    int lane = threadIdx.x & 31;
    int which = gw & 1;
    int row = gw >> 1;
    float* ptr = which ? k : q;

    size_t base = (size_t)(row >> 4) * D_MODEL + (size_t)(row & 15) * 64;
    int s = (row >> 4) & (N_CTX - 1);

    float2 xv = *(float2*)&ptr[base + lane * 2];
    float ss = xv.x * xv.x + xv.y * xv.y;
#pragma unroll
    for (int o = 16; o; o >>= 1) ss += __shfl_xor_sync(0xffffffffu, ss, o);
    float r = rsqrtf(ss * (1.0f / 64.0f) + 1.1920929e-07f);

    float y0 = xv.x * r * w[lane * 2];
    float y1 = xv.y * r * w[lane * 2 + 1];

    int j0 = (2 * lane) & 31;
    int j1 = (2 * lane + 1) & 31;
    float c0 = g_cos[s * 32 + j0], s0 = g_sin[s * 32 + j0];
    float c1 = g_cos[s * 32 + j1], s1 = g_sin[s * 32 + j1];

    float2 o;
    o.x = y0 * c0 - y1 * s0;
    o.y = y1 * c1 + y0 * s1;
    *(float2*)&ptr[base + lane * 2] = o;
}

// ---------------- fused quadratic causal attention, TF32 mma ----------------
// CTA: 128 threads (4 warps), q-tile 128; warp owns 32 q-rows x full 64-k.
// SHUFFLE-FREE P reuse: V rows permuted within each 8-block by l(r)=(r&1)*4+(r>>1)
// so the S C-fragment maps directly onto the next mma's A-fragment slots.
#define ATTN_SMEM (16384 * 4)   /* 64 KB: Qs 32KB | Ks 16KB | Vs 16KB */

__global__ __launch_bounds__(128)
void attn_tc_kernel(const float* __restrict__ Q, const float* __restrict__ Kg,
                    const float* __restrict__ V, float* __restrict__ Z)
{
    extern __shared__ float sm[];
    float4* Qs4 = (float4*)sm;        // [ks8][mt8][lane32] float4 frags
    float*  KsF = sm + 8192;          // frag-major K
    float*  VsF = sm + 12288;         // frag-major V (k-permuted)

    const int tid = threadIdx.x;
    const int lane = tid & 31;
    const int wp = tid >> 5;                 // warp 0..3
    const int g = lane >> 2, t = lane & 3;
    const int bh = blockIdx.y;
    const int b = bh >> 4, h = bh & 15;
    const int jt = (int)gridDim.x - 1 - (int)blockIdx.x;   // big tiles first
    const size_t base = (size_t)(b * N_CTX) * D_MODEL + h * 64;
    const int nkt = 2 * jt + 2;

    // ---- Q tile (128 x 64) -> fragment-major smem, once ----
    {
        const int r0 = tid >> 4, c4 = tid & 15;
        const int qks = c4 >> 1, th = c4 & 1;
        const int kx = qks & 3;
#pragma unroll
        for (int j = 0; j < 16; j++) {
            int r = 8 * j + r0;
            int mt = r >> 4, gg = r & 15;
            int comp = (gg >> 3) + 2 * th;
            int gq = gg & 7;
            float4 qv = *(const float4*)&Q[base + (size_t)(jt * 128 + r) * D_MODEL + c4 * 4];
            float vals[4] = {qv.x, qv.y, qv.z, qv.w};
            float* dst = (float*)Qs4 + ((qks * 8 + mt) * 32) * 4 + comp;
#pragma unroll
            for (int i = 0; i < 4; i++)
                dst[(4 * gq + (i ^ kx)) * 4] = ftf(vals[i]);
        }
    }

    float zacc[2][8][4];
#pragma unroll
    for (int mm = 0; mm < 2; mm++)
#pragma unroll
        for (int i = 0; i < 8; i++)
#pragma unroll
            for (int j = 0; j < 4; j++) zacc[mm][i][j] = 0.f;

    // K loader: rows krow0+8j, cols kcol4*4..+3
    const int krow0 = tid >> 4, kcol4 = tid & 15;
    const int kksp = kcol4 >> 2, kcomp = kcol4 & 3;
    // V loader: row vrow, cols (vh + 2j)*4..+3, with within-8 row permutation:
    // logical l = (rr&1)*4 + (rr>>1)  =>  t-lane = rr>>1, comp = (rr&1) | (kh<<1)
    const int vrow = tid & 63, vh = tid >> 6;
    const int vcp = vrow >> 4;
    const int vrr = vrow & 7;
    const int vkh = (vrow >> 3) & 1;
    const int vtt = vrr >> 1;
    const int vcomp = (vrr & 1) | (vkh << 1);
    const int vg0 = vh * 4;
    const int vsw = vtt ^ (vcp & 3);

    const float* kbase = Kg + base;
    const float* vbase = V + base;

    const float inv64 = 1.0f / 64.0f;
    const int qbase = jt * 128 + wp * 32;

    for (int kt = 0; kt < nkt; ++kt) {
        const int ktb = kt * 64;
        __syncthreads();   // previous iteration's consumers done (covers Q store at kt=0)
        // ---- K tile -> fragment-major ----
#pragma unroll
        for (int j = 0; j < 8; j++) {
            float4 kv = *(const float4*)&kbase[(size_t)(ktb + krow0 + 8 * j) * D_MODEL + kcol4 * 4];
            int bb = (kksp * 8 + j) * 32 + krow0 * 4;
            KsF[(bb + (0 ^ kksp)) * 4 + kcomp] = ftf(kv.x);
            KsF[(bb + (1 ^ kksp)) * 4 + kcomp] = ftf(kv.y);
            KsF[(bb + (2 ^ kksp)) * 4 + kcomp] = ftf(kv.z);
            KsF[(bb + (3 ^ kksp)) * 4 + kcomp] = ftf(kv.w);
        }
        // ---- V tile -> fragment-major (k-permuted, cp-xor swizzled) ----
#pragma unroll
        for (int j = 0; j < 8; j++) {
            float4 vv = *(const float4*)&vbase[(size_t)(ktb + vrow) * D_MODEL + (vh + 2 * j) * 4];
            int bb = (vcp * 8 + j) * 32 + vg0 * 4 + vsw;
            VsF[(bb + 0)  * 4 + vcomp] = ftf(vv.x);
            VsF[(bb + 4)  * 4 + vcomp] = ftf(vv.y);
            VsF[(bb + 8)  * 4 + vcomp] = ftf(vv.z);
            VsF[(bb + 12) * 4 + vcomp] = ftf(vv.w);
        }
        __syncthreads();

        const float4* KsP = (const float4*)KsF;
        const float4* VsP = (const float4*)VsF;

        // ---- GEMM1: S[32 x 64] per warp ----
        float sacc[2][8][4];
#pragma unroll
        for (int mm = 0; mm < 2; mm++)
#pragma unroll
            for (int i = 0; i < 8; i++)
#pragma unroll
                for (int j = 0; j < 4; j++) sacc[mm][i][j] = 0.f;

#pragma unroll
        for (int ksp = 0; ksp < 4; ksp++) {
            int slot = (lane & 28) | ((lane & 3) ^ ksp);
            float4 kb[8];
#pragma unroll
            for (int nt = 0; nt < 8; nt++)
                kb[nt] = KsP[(ksp * 8 + nt) * 32 + slot];
#pragma unroll
            for (int kh = 0; kh < 2; kh++) {
                int ks = ksp * 2 + kh;
                int qslot = (lane & 28) | ((lane & 3) ^ (ks & 3));
                float4 qa0 = Qs4[(ks * 8 + wp * 2 + 0) * 32 + qslot];
                float4 qa1 = Qs4[(ks * 8 + wp * 2 + 1) * 32 + qslot];
                float a0[4] = {qa0.x, qa0.y, qa0.z, qa0.w};
                float a1[4] = {qa1.x, qa1.y, qa1.z, qa1.w};
#pragma unroll
                for (int nt = 0; nt < 8; nt++) {
                    float bfr[2];
                    if (kh == 0) { bfr[0] = kb[nt].x; bfr[1] = kb[nt].y; }
                    else         { bfr[0] = kb[nt].z; bfr[1] = kb[nt].w; }
                    mma8(sacc[0][nt], a0, bfr);
                    mma8(sacc[1][nt], a1, bfr);
                }
            }
        }

        // ---- P = (S/64)^2 * causal; direct C->A rename; GEMM2 ----
#pragma unroll
        for (int cp = 0; cp < 4; cp++) {
            int vslot = (lane & 28) | ((lane & 3) ^ (cp & 3));
            float4 vb[8];
#pragma unroll
            for (int dn = 0; dn < 8; dn++)
                vb[dn] = VsP[(cp * 8 + dn) * 32 + vslot];
#pragma unroll
            for (int kh = 0; kh < 2; kh++) {
                int c = cp * 2 + kh;
                int kc = ktb + c * 8 + 2 * t;
#pragma unroll
                for (int mm = 0; mm < 2; mm++) {
                    int qr0 = qbase + mm * 16 + g;
                    int qr1 = qr0 + 8;
                    float s0 = sacc[mm][c][0] * inv64; s0 *= s0; if (kc > qr0)     s0 = 0.f;
                    float s1 = sacc[mm][c][1] * inv64; s1 *= s1; if (kc + 1 > qr0) s1 = 0.f;
                    float s2 = sacc[mm][c][2] * inv64; s2 *= s2; if (kc > qr1)     s2 = 0.f;
                    float s3 = sacc[mm][c][3] * inv64; s3 *= s3; if (kc + 1 > qr1) s3 = 0.f;
                    // A-frag slots: (g,lt)=col 2t -> s0 ; (g+8,lt)=s2 ; (g,lt+4)=col 2t+1 -> s1 ; (g+8,lt+4)=s3
                    float af[4];
                    af[0] = ftf(s0);
                    af[1] = ftf(s2);
                    af[2] = ftf(s1);
                    af[3] = ftf(s3);
#pragma unroll
                    for (int dn = 0; dn < 8; dn++) {
                        float bfr[2];
                        if (kh == 0) { bfr[0] = vb[dn].x; bfr[1] = vb[dn].y; }
                        else         { bfr[0] = vb[dn].z; bfr[1] = vb[dn].w; }
                        mma8(zacc[mm][dn], af, bfr);
                    }
                }
            }
        }
    }

    // ---- write Z ----
#pragma unroll
    for (int mm = 0; mm < 2; mm++) {
        int qr0 = qbase + mm * 16 + g;
        int qr1 = qr0 + 8;
#pragma unroll
        for (int dn = 0; dn < 8; dn++) {
            int col = dn * 8 + 2 * t;
            *(float2*)&Z[base + (size_t)qr0 * D_MODEL + col] =
                make_float2(zacc[mm][dn][0], zacc[mm][dn][1]);
            *(float2*)&Z[base + (size_t)qr1 * D_MODEL + col] =
                make_float2(zacc[mm][dn][2], zacc[mm][dn][3]);
        }
    }
}

// ---------------- launch ----------------
extern "C" void kernel_launch(void* const* d_in, const int* in_sizes, int n_in,
                              void* d_out, int out_size)
{
    const float* x  = (const float*)d_in[0];
    const float* Wq = (const float*)d_in[1];
    const float* bq = (const float*)d_in[2];
    const float* Wk = (const float*)d_in[3];
    const float* bk = (const float*)d_in[4];
    const float* Wv = (const float*)d_in[5];
    const float* bv = (const float*)d_in[6];
    const float* Wo = (const float*)d_in[7];
    const float* nw = (const float*)d_in[8];
    float* out = (float*)d_out;

    float *q, *k, *v, *z;
    cudaGetSymbolAddress((void**)&q, g_q);
    cudaGetSymbolAddress((void**)&k, g_k);
    cudaGetSymbolAddress((void**)&v, g_v);
    cudaGetSymbolAddress((void**)&z, g_z);

    cudaFuncSetAttribute(attn_tc_kernel, cudaFuncAttributeMaxDynamicSharedMemorySize, ATTN_SMEM);

    rope_cache_kernel<<<64, 1024>>>();

    GemmJobs jq;
    jq.W[0] = Wq; jq.W[1] = Wk; jq.W[2] = Wv;
    jq.bias[0] = bq; jq.bias[1] = bk; jq.bias[2] = bv;
    jq.res[0] = nullptr; jq.res[1] = nullptr; jq.res[2] = nullptr;
    jq.out[0] = q; jq.out[1] = k; jq.out[2] = v;
    gemm_tc_kernel<<<dim3(D_MODEL / 128, MTOT / 128, 3), 256>>>(x, jq, MTOT, D_MODEL, D_MODEL);

    norm_rope_kernel<<<16384, 256>>>(q, k, nw);

    attn_tc_kernel<<<dim3(16, 32), 128, ATTN_SMEM>>>(q, k, v, z);

    GemmJobs jo;
    jo.W[0] = Wo; jo.W[1] = nullptr; jo.W[2] = nullptr;
    jo.bias[0] = nullptr; jo.bias[1] = nullptr; jo.bias[2] = nullptr;
    jo.res[0] = x; jo.res[1] = nullptr; jo.res[2] = nullptr;
    jo.out[0] = out; jo.out[1] = nullptr; jo.out[2] = nullptr;
    gemm_tc_kernel<<<dim3(D_MODEL / 128, MTOT / 128, 1), 256>>>(z, jo, MTOT, D_MODEL, D_MODEL);
}